// round 1
// baseline (speedup 1.0000x reference)
#include <cuda_runtime.h>
#include <cuda_bf16.h>
#include <math.h>

// Problem constants
#define BATCH   32
#define SEQ     2048
#define DMODEL  256
#define HIDDEN  512
#define INNER   1024
#define TOKENS  (BATCH * SEQ)           // 65536

// ---------------------------------------------------------------------------
// Scratch buffers (static device memory; no runtime allocation allowed)
// ---------------------------------------------------------------------------
__device__ float g_xz   [(size_t)TOKENS * 1024];   // x @ w_in  -> [xh | z]
__device__ float g_xc   [(size_t)TOKENS * HIDDEN]; // silu(conv(xh)+cb)
__device__ float g_zs   [(size_t)TOKENS * HIDDEN]; // silu(z)
__device__ float g_gates[(size_t)TOKENS * 1024];   // xc @ w_gates + b
__device__ float g_alpha[(size_t)TOKENS * HIDDEN];
__device__ float g_betap[(size_t)TOKENS * HIDDEN];
__device__ float g_gh   [(size_t)TOKENS * HIDDEN]; // silu(z) * h
__device__ float g_y    [(size_t)TOKENS * DMODEL]; // (silu(z)*h) @ w_out
__device__ float g_hs   [(size_t)TOKENS * DMODEL]; // LN1(y + x)
__device__ float g_u    [(size_t)TOKENS * INNER];  // silu(hs@W1+b1)
__device__ float g_ff   [(size_t)TOKENS * DMODEL]; // u@W2+b2

__device__ __forceinline__ float siluf(float v) {
    return v / (1.0f + __expf(-v));
}
__device__ __forceinline__ float sigmoidf_(float v) {
    return 1.0f / (1.0f + __expf(-v));
}

// ---------------------------------------------------------------------------
// SGEMM: C[M,N] = A[M,K] @ B[K,N] (+bias)(+silu). Row-major everywhere.
// Block tile 128x128, K-step 8, 256 threads, 8x8 per thread.
// Requires: M%128==0, N%128==0, K%8==0 (true for all calls here).
// EPI: 0 = none, 1 = +bias, 2 = silu(+bias)
// ---------------------------------------------------------------------------
template <int EPI>
__global__ void __launch_bounds__(256) sgemm_k(
    const float* __restrict__ A, const float* __restrict__ B,
    const float* __restrict__ bias, float* __restrict__ C,
    int M, int N, int K)
{
    __shared__ float As[8][128];
    __shared__ float Bs[8][128];

    const int tid = threadIdx.x;
    const int bm = blockIdx.y * 128;
    const int bn = blockIdx.x * 128;

    // A tile load mapping: 128 rows x 8 cols via float4 (one per thread)
    const int arow = tid >> 1;          // 0..127
    const int acol = (tid & 1) * 4;     // 0 or 4
    // B tile load mapping: 8 rows x 128 cols via float4
    const int brow = tid >> 5;          // 0..7
    const int bcol = (tid & 31) * 4;    // 0..124

    const int ty = tid >> 4;            // 0..15
    const int tx = tid & 15;            // 0..15

    float acc[8][8];
    #pragma unroll
    for (int i = 0; i < 8; i++)
        #pragma unroll
        for (int j = 0; j < 8; j++) acc[i][j] = 0.0f;

    const float* Aptr = A + (size_t)(bm + arow) * K + acol;
    const float* Bptr = B + (size_t)brow * N + bn + bcol;

    for (int k0 = 0; k0 < K; k0 += 8) {
        float4 av = *reinterpret_cast<const float4*>(Aptr + k0);
        As[acol + 0][arow] = av.x;
        As[acol + 1][arow] = av.y;
        As[acol + 2][arow] = av.z;
        As[acol + 3][arow] = av.w;
        float4 bv = *reinterpret_cast<const float4*>(Bptr + (size_t)k0 * N);
        *reinterpret_cast<float4*>(&Bs[brow][bcol]) = bv;
        __syncthreads();

        #pragma unroll
        for (int k = 0; k < 8; k++) {
            float a[8], b[8];
            float4 a0 = *reinterpret_cast<const float4*>(&As[k][ty * 8]);
            float4 a1 = *reinterpret_cast<const float4*>(&As[k][ty * 8 + 4]);
            a[0]=a0.x; a[1]=a0.y; a[2]=a0.z; a[3]=a0.w;
            a[4]=a1.x; a[5]=a1.y; a[6]=a1.z; a[7]=a1.w;
            float4 b0 = *reinterpret_cast<const float4*>(&Bs[k][tx * 8]);
            float4 b1 = *reinterpret_cast<const float4*>(&Bs[k][tx * 8 + 4]);
            b[0]=b0.x; b[1]=b0.y; b[2]=b0.z; b[3]=b0.w;
            b[4]=b1.x; b[5]=b1.y; b[6]=b1.z; b[7]=b1.w;
            #pragma unroll
            for (int i = 0; i < 8; i++)
                #pragma unroll
                for (int j = 0; j < 8; j++)
                    acc[i][j] = fmaf(a[i], b[j], acc[i][j]);
        }
        __syncthreads();
    }

    // Epilogue
    #pragma unroll
    for (int i = 0; i < 8; i++) {
        const int row = bm + ty * 8 + i;
        float* crow = C + (size_t)row * N + bn + tx * 8;
        #pragma unroll
        for (int jj = 0; jj < 2; jj++) {
            float4 v;
            float vv[4];
            #pragma unroll
            for (int j = 0; j < 4; j++) {
                float t = acc[i][jj * 4 + j];
                if (EPI >= 1) t += bias[bn + tx * 8 + jj * 4 + j];
                if (EPI == 2) t = siluf(t);
                vv[j] = t;
            }
            v.x = vv[0]; v.y = vv[1]; v.z = vv[2]; v.w = vv[3];
            *reinterpret_cast<float4*>(crow + jj * 4) = v;
        }
    }
}

// ---------------------------------------------------------------------------
// Depthwise causal conv (KSIZE=4) + SiLU, and silu(z)
// xz layout: [token, 1024] with cols 0..511 = xh, 512..1023 = z
// ---------------------------------------------------------------------------
__global__ void conv_silu_k(const float* __restrict__ xz,
                            const float* __restrict__ cw,
                            const float* __restrict__ cb,
                            float* __restrict__ xc,
                            float* __restrict__ zs)
{
    int idx = blockIdx.x * blockDim.x + threadIdx.x; // over TOKENS*512
    if (idx >= TOKENS * HIDDEN) return;
    int h  = idx & (HIDDEN - 1);
    int bt = idx >> 9;               // token index (b*SEQ + t)
    int t  = bt & (SEQ - 1);

    const float* row = xz + (size_t)bt * 1024;
    float w0 = cw[h * 4 + 0], w1 = cw[h * 4 + 1];
    float w2 = cw[h * 4 + 2], w3 = cw[h * 4 + 3];

    float acc = w3 * row[h];
    if (t >= 1) acc = fmaf(w2, row[h - 1024], acc);
    if (t >= 2) acc = fmaf(w1, row[h - 2048], acc);
    if (t >= 3) acc = fmaf(w0, row[h - 3072], acc);
    acc += cb[h];
    xc[idx] = siluf(acc);

    float z = row[h + HIDDEN];
    zs[idx] = siluf(z);
}

// ---------------------------------------------------------------------------
// Gate nonlinearity: alpha, beta' from gates + xc
// ---------------------------------------------------------------------------
__global__ void gate_k(const float* __restrict__ gates,
                       const float* __restrict__ Lambda,
                       const float* __restrict__ xc,
                       float* __restrict__ alpha,
                       float* __restrict__ betap)
{
    int idx = blockIdx.x * blockDim.x + threadIdx.x; // over TOKENS*512
    if (idx >= TOKENS * HIDDEN) return;
    int h   = idx & (HIDDEN - 1);
    int tok = idx >> 9;

    float rec = gates[(size_t)tok * 1024 + h];
    float inp = gates[(size_t)tok * 1024 + h + HIDDEN];
    float lam = Lambda[h];
    float sp  = log1pf(__expf(lam));            // softplus (lam in [-7,-2], safe)
    float a   = __expf(-sp * sigmoidf_(rec));
    float beta = sqrtf(1.0f - a * a + 1e-8f) * sigmoidf_(inp);
    alpha[idx] = a;
    betap[idx] = beta * xc[idx];
}

// ---------------------------------------------------------------------------
// Sequential scan over time per (b, h) channel; fused with g = silu(z)*h
// 16384 channels; layout is [b, t, h] with h fastest -> coalesced per warp.
// ---------------------------------------------------------------------------
__global__ void scan_k(const float* __restrict__ alpha,
                       const float* __restrict__ betap,
                       const float* __restrict__ zs,
                       float* __restrict__ gh)
{
    int c = blockIdx.x * blockDim.x + threadIdx.x; // 0..16383 (b*512 + h)
    if (c >= BATCH * HIDDEN) return;
    int b = c >> 9;
    int h = c & (HIDDEN - 1);
    size_t base = (size_t)b * SEQ * HIDDEN + h;

    float state = 0.0f;
    #pragma unroll 4
    for (int t = 0; t < SEQ; t++) {
        size_t off = base + (size_t)t * HIDDEN;
        state = fmaf(alpha[off], state, betap[off]);
        gh[off] = state * zs[off];
    }
}

// ---------------------------------------------------------------------------
// LayerNorm over D=256: out = LN(a + res) * gamma + beta
// One block (256 threads) per token.
// ---------------------------------------------------------------------------
__global__ void ln_k(const float* __restrict__ a,
                     const float* __restrict__ res,
                     const float* __restrict__ gamma,
                     const float* __restrict__ beta,
                     float* __restrict__ out)
{
    int tok = blockIdx.x;
    int i = threadIdx.x;
    size_t off = (size_t)tok * DMODEL + i;
    float v = a[off] + res[off];

    float s = v, s2 = v * v;
    #pragma unroll
    for (int o = 16; o > 0; o >>= 1) {
        s  += __shfl_xor_sync(0xffffffffu, s,  o);
        s2 += __shfl_xor_sync(0xffffffffu, s2, o);
    }
    __shared__ float sh[2][8];
    int w = i >> 5, l = i & 31;
    if (l == 0) { sh[0][w] = s; sh[1][w] = s2; }
    __syncthreads();
    if (w == 0) {
        float ts  = (l < 8) ? sh[0][l] : 0.0f;
        float ts2 = (l < 8) ? sh[1][l] : 0.0f;
        #pragma unroll
        for (int o = 4; o > 0; o >>= 1) {
            ts  += __shfl_xor_sync(0xffffffffu, ts,  o);
            ts2 += __shfl_xor_sync(0xffffffffu, ts2, o);
        }
        if (l == 0) { sh[0][0] = ts; sh[1][0] = ts2; }
    }
    __syncthreads();
    float mean = sh[0][0] * (1.0f / DMODEL);
    float var  = sh[1][0] * (1.0f / DMODEL) - mean * mean;
    float inv  = rsqrtf(var + 1e-12f);
    out[off] = (v - mean) * inv * gamma[i] + beta[i];
}

// ---------------------------------------------------------------------------
// Host launcher
// ---------------------------------------------------------------------------
extern "C" void kernel_launch(void* const* d_in, const int* in_sizes, int n_in,
                              void* d_out, int out_size)
{
    const float* x      = (const float*)d_in[0];
    const float* w_in   = (const float*)d_in[1];
    const float* conv_w = (const float*)d_in[2];
    const float* conv_b = (const float*)d_in[3];
    const float* w_gate = (const float*)d_in[4];
    const float* b_gate = (const float*)d_in[5];
    const float* Lambda = (const float*)d_in[6];
    const float* w_out  = (const float*)d_in[7];
    const float* ln1_g  = (const float*)d_in[8];
    const float* ln1_b  = (const float*)d_in[9];
    const float* ffn_w1 = (const float*)d_in[10];
    const float* ffn_b1 = (const float*)d_in[11];
    const float* ffn_w2 = (const float*)d_in[12];
    const float* ffn_b2 = (const float*)d_in[13];
    const float* ln2_g  = (const float*)d_in[14];
    const float* ln2_b  = (const float*)d_in[15];
    float* out = (float*)d_out;

    float *xz, *xc, *zs, *gates, *alpha, *betap, *gh, *y, *hs, *u, *ff;
    cudaGetSymbolAddress((void**)&xz,    g_xz);
    cudaGetSymbolAddress((void**)&xc,    g_xc);
    cudaGetSymbolAddress((void**)&zs,    g_zs);
    cudaGetSymbolAddress((void**)&gates, g_gates);
    cudaGetSymbolAddress((void**)&alpha, g_alpha);
    cudaGetSymbolAddress((void**)&betap, g_betap);
    cudaGetSymbolAddress((void**)&gh,    g_gh);
    cudaGetSymbolAddress((void**)&y,     g_y);
    cudaGetSymbolAddress((void**)&hs,    g_hs);
    cudaGetSymbolAddress((void**)&u,     g_u);
    cudaGetSymbolAddress((void**)&ff,    g_ff);

    const int M = TOKENS;
    dim3 thr(256);

    // 1) xz = x @ w_in                      [65536,256]@[256,1024]
    sgemm_k<0><<<dim3(1024 / 128, M / 128), thr>>>(x, w_in, nullptr, xz, M, 1024, DMODEL);

    // 2) depthwise conv + silu; silu(z)
    conv_silu_k<<<(TOKENS * HIDDEN) / 256, thr>>>(xz, conv_w, conv_b, xc, zs);

    // 3) gates = xc @ w_gates + b_gates     [65536,512]@[512,1024]
    sgemm_k<1><<<dim3(1024 / 128, M / 128), thr>>>(xc, w_gate, b_gate, gates, M, 1024, HIDDEN);

    // 4) alpha / beta'
    gate_k<<<(TOKENS * HIDDEN) / 256, thr>>>(gates, Lambda, xc, alpha, betap);

    // 5) scan + g = silu(z)*h
    scan_k<<<(BATCH * HIDDEN) / 256, thr>>>(alpha, betap, zs, gh);

    // 6) y = g @ w_out                      [65536,512]@[512,256]
    sgemm_k<0><<<dim3(256 / 128, M / 128), thr>>>(gh, w_out, nullptr, y, M, DMODEL, HIDDEN);

    // 7) hs = LN1(y + x)
    ln_k<<<TOKENS, DMODEL>>>(y, x, ln1_g, ln1_b, hs);

    // 8) u = silu(hs @ ffn_w1 + b1)         [65536,256]@[256,1024]
    sgemm_k<2><<<dim3(1024 / 128, M / 128), thr>>>(hs, ffn_w1, ffn_b1, u, M, INNER, DMODEL);

    // 9) ff = u @ ffn_w2 + b2               [65536,1024]@[1024,256]
    sgemm_k<1><<<dim3(256 / 128, M / 128), thr>>>(u, ffn_w2, ffn_b2, ff, M, DMODEL, INNER);

    // 10) out = LN2(ff + hs)
    ln_k<<<TOKENS, DMODEL>>>(ff, hs, ln2_g, ln2_b, out);
}

// round 2
// speedup vs baseline: 2.8742x; 2.8742x over previous
#include <cuda_runtime.h>
#include <cuda_bf16.h>
#include <math.h>

// Problem constants
#define BATCH   32
#define SEQ     2048
#define DMODEL  256
#define HIDDEN  512
#define INNER   1024
#define TOKENS  (BATCH * SEQ)           // 65536
#define NCH     (BATCH * HIDDEN)        // 16384 scan channels
#define NCHUNK  16
#define TCHUNK  (SEQ / NCHUNK)          // 128

// ---------------------------------------------------------------------------
// Scratch (static device memory)
// ---------------------------------------------------------------------------
__device__ float g_xz   [(size_t)TOKENS * 1024];   // [xh | z]
__device__ float g_xc   [(size_t)TOKENS * HIDDEN];
__device__ float g_gates[(size_t)TOKENS * 1024];
__device__ float g_gh   [(size_t)TOKENS * HIDDEN];
__device__ float g_y    [(size_t)TOKENS * DMODEL];
__device__ float g_hs   [(size_t)TOKENS * DMODEL];
__device__ float g_u    [(size_t)TOKENS * INNER];
__device__ float g_ff   [(size_t)TOKENS * DMODEL];
__device__ float g_chA  [(size_t)NCH * NCHUNK];
__device__ float g_chB  [(size_t)NCH * NCHUNK];
__device__ float g_pref [(size_t)NCH * NCHUNK];

__device__ __forceinline__ float siluf(float v)     { return v / (1.0f + __expf(-v)); }
__device__ __forceinline__ float sigmoidf_(float v) { return 1.0f / (1.0f + __expf(-v)); }

// ---------------------------------------------------------------------------
// cp.async helpers
// ---------------------------------------------------------------------------
__device__ __forceinline__ void cp_async16(void* smem, const void* gmem) {
    unsigned s = (unsigned)__cvta_generic_to_shared(smem);
    asm volatile("cp.async.cg.shared.global [%0], [%1], 16;\n" :: "r"(s), "l"(gmem));
}
__device__ __forceinline__ void cp_commit() { asm volatile("cp.async.commit_group;\n"); }
template<int N> __device__ __forceinline__ void cp_wait() {
    asm volatile("cp.async.wait_group %0;\n" :: "n"(N));
}

__device__ __forceinline__ void mma_tf32(float c[4], const unsigned a[4], const unsigned b[2]) {
    asm volatile(
        "mma.sync.aligned.m16n8k8.row.col.f32.tf32.tf32.f32 "
        "{%0,%1,%2,%3}, {%4,%5,%6,%7}, {%8,%9}, {%0,%1,%2,%3};\n"
        : "+f"(c[0]), "+f"(c[1]), "+f"(c[2]), "+f"(c[3])
        : "r"(a[0]), "r"(a[1]), "r"(a[2]), "r"(a[3]), "r"(b[0]), "r"(b[1]));
}

// ---------------------------------------------------------------------------
// Tensor-core tf32 GEMM: C[M,N] = A[M,K] @ B[K,N] (+bias)(+silu)
// 128x128 block tile, BK=16, 8 warps (2x4), warp tile 64x32.
// Requires M%128==0, N%128==0, K%16==0.
// EPI: 0=none, 1=+bias, 2=silu(+bias)
// ---------------------------------------------------------------------------
#define BM 128
#define BN 128
#define BKT 16
#define AS_STR 20    // BKT + 4  (floats) -> conflict-free A frag loads
#define BS_STR 136   // BN + 8   (floats) -> conflict-free B frag loads

template<int EPI>
__global__ void __launch_bounds__(256) tc_gemm(
    const float* __restrict__ A, const float* __restrict__ B,
    const float* __restrict__ bias, float* __restrict__ C,
    int M, int N, int K)
{
    __shared__ float As[2][BM * AS_STR];
    __shared__ float Bs[2][BKT * BS_STR];

    const int tid  = threadIdx.x;
    const int warp = tid >> 5;
    const int lane = tid & 31;
    const int g    = lane >> 2;   // 0..7
    const int tg   = lane & 3;    // 0..3

    const int bm = blockIdx.y * BM;
    const int bn = blockIdx.x * BN;
    const int wm = (warp >> 2) * 64;   // 0 / 64
    const int wn = (warp & 3) * 32;    // 0..96

    // global->smem load mapping
    const int a_row = tid >> 2;        // 0..63 (and +64)
    const int a_col = (tid & 3) * 4;   // 0,4,8,12
    const int b_row = tid >> 4;        // 0..15
    const int b_col = (tid & 15) * 4;  // 0..60 (and +64)

    float acc[4][4][4];
    #pragma unroll
    for (int mi = 0; mi < 4; mi++)
        #pragma unroll
        for (int ni = 0; ni < 4; ni++)
            #pragma unroll
            for (int r = 0; r < 4; r++) acc[mi][ni][r] = 0.0f;

    const int KT = K / BKT;

    const float* Ag0 = A + (size_t)(bm + a_row) * K + a_col;
    const float* Ag1 = Ag0 + (size_t)64 * K;
    const float* Bg  = B + (size_t)b_row * N + bn + b_col;

    // prologue: load tile 0
    {
        cp_async16(&As[0][a_row * AS_STR + a_col], Ag0);
        cp_async16(&As[0][(a_row + 64) * AS_STR + a_col], Ag1);
        cp_async16(&Bs[0][b_row * BS_STR + b_col], Bg);
        cp_async16(&Bs[0][b_row * BS_STR + b_col + 64], Bg + 64);
        cp_commit();
    }

    for (int kt = 0; kt < KT; kt++) {
        const int buf = kt & 1;
        if (kt + 1 < KT) {
            const int nb = buf ^ 1;
            const int ko = (kt + 1) * BKT;
            cp_async16(&As[nb][a_row * AS_STR + a_col], Ag0 + ko);
            cp_async16(&As[nb][(a_row + 64) * AS_STR + a_col], Ag1 + ko);
            cp_async16(&Bs[nb][b_row * BS_STR + b_col], Bg + (size_t)ko * N);
            cp_async16(&Bs[nb][b_row * BS_STR + b_col + 64], Bg + (size_t)ko * N + 64);
            cp_commit();
            cp_wait<1>();
        } else {
            cp_wait<0>();
        }
        __syncthreads();

        const float* as = As[buf];
        const float* bs = Bs[buf];
        #pragma unroll
        for (int ks = 0; ks < 2; ks++) {
            const int k0 = ks * 8;
            unsigned af[4][4];
            #pragma unroll
            for (int mi = 0; mi < 4; mi++) {
                const int mr = wm + mi * 16;
                af[mi][0] = __float_as_uint(as[(mr + g)     * AS_STR + k0 + tg]);
                af[mi][1] = __float_as_uint(as[(mr + g + 8) * AS_STR + k0 + tg]);
                af[mi][2] = __float_as_uint(as[(mr + g)     * AS_STR + k0 + tg + 4]);
                af[mi][3] = __float_as_uint(as[(mr + g + 8) * AS_STR + k0 + tg + 4]);
            }
            unsigned bf[4][2];
            #pragma unroll
            for (int ni = 0; ni < 4; ni++) {
                const int nc = wn + ni * 8;
                bf[ni][0] = __float_as_uint(bs[(k0 + tg)     * BS_STR + nc + g]);
                bf[ni][1] = __float_as_uint(bs[(k0 + tg + 4) * BS_STR + nc + g]);
            }
            #pragma unroll
            for (int mi = 0; mi < 4; mi++)
                #pragma unroll
                for (int ni = 0; ni < 4; ni++)
                    mma_tf32(acc[mi][ni], af[mi], bf[ni]);
        }
        __syncthreads();
    }

    // epilogue
    #pragma unroll
    for (int mi = 0; mi < 4; mi++) {
        const int r0 = bm + wm + mi * 16 + g;
        #pragma unroll
        for (int ni = 0; ni < 4; ni++) {
            const int col = bn + wn + ni * 8 + tg * 2;
            float bia0 = 0.f, bia1 = 0.f;
            if (EPI >= 1) { bia0 = bias[col]; bia1 = bias[col + 1]; }
            float v0 = acc[mi][ni][0] + bia0;
            float v1 = acc[mi][ni][1] + bia1;
            float v2 = acc[mi][ni][2] + bia0;
            float v3 = acc[mi][ni][3] + bia1;
            if (EPI == 2) { v0 = siluf(v0); v1 = siluf(v1); v2 = siluf(v2); v3 = siluf(v3); }
            *reinterpret_cast<float2*>(C + (size_t)r0 * N + col)       = make_float2(v0, v1);
            *reinterpret_cast<float2*>(C + (size_t)(r0 + 8) * N + col) = make_float2(v2, v3);
        }
    }
}

// ---------------------------------------------------------------------------
// Depthwise causal conv (K=4) + SiLU, float4-vectorized over h.
// Reads xh half of xz, writes xc.
// ---------------------------------------------------------------------------
__global__ void conv_silu_k(const float* __restrict__ xz,
                            const float* __restrict__ cw,
                            const float* __restrict__ cb,
                            float* __restrict__ xc)
{
    int idx = blockIdx.x * blockDim.x + threadIdx.x; // over TOKENS * 128
    if (idx >= TOKENS * (HIDDEN / 4)) return;
    int h4  = idx & 127;
    int tok = idx >> 7;
    int t   = tok & (SEQ - 1);
    int h   = h4 * 4;

    const float* row = xz + (size_t)tok * 1024 + h;
    float4 c0 = *reinterpret_cast<const float4*>(row);
    float4 c1 = (t >= 1) ? *reinterpret_cast<const float4*>(row - 1024) : make_float4(0,0,0,0);
    float4 c2 = (t >= 2) ? *reinterpret_cast<const float4*>(row - 2048) : make_float4(0,0,0,0);
    float4 c3 = (t >= 3) ? *reinterpret_cast<const float4*>(row - 3072) : make_float4(0,0,0,0);

    float4 out;
    float4 bb = *reinterpret_cast<const float4*>(cb + h);
    {
        float4 w = *reinterpret_cast<const float4*>(cw + (size_t)(h + 0) * 4);
        out.x = siluf(fmaf(w.w, c0.x, fmaf(w.z, c1.x, fmaf(w.y, c2.x, fmaf(w.x, c3.x, bb.x)))));
    }
    {
        float4 w = *reinterpret_cast<const float4*>(cw + (size_t)(h + 1) * 4);
        out.y = siluf(fmaf(w.w, c0.y, fmaf(w.z, c1.y, fmaf(w.y, c2.y, fmaf(w.x, c3.y, bb.y)))));
    }
    {
        float4 w = *reinterpret_cast<const float4*>(cw + (size_t)(h + 2) * 4);
        out.z = siluf(fmaf(w.w, c0.z, fmaf(w.z, c1.z, fmaf(w.y, c2.z, fmaf(w.x, c3.z, bb.z)))));
    }
    {
        float4 w = *reinterpret_cast<const float4*>(cw + (size_t)(h + 3) * 4);
        out.w = siluf(fmaf(w.w, c0.w, fmaf(w.z, c1.w, fmaf(w.y, c2.w, fmaf(w.x, c3.w, bb.w)))));
    }
    *reinterpret_cast<float4*>(xc + (size_t)tok * HIDDEN + h) = out;
}

// ---------------------------------------------------------------------------
// Chunked scan, fused gate nonlinearity. id = chunk*NCH + (b*512+h).
// ---------------------------------------------------------------------------
__device__ __forceinline__ void gate_ab(float rec, float inp, float sp, float xcv,
                                        float& a, float& bp)
{
    a = __expf(-sp * sigmoidf_(rec));
    float beta = sqrtf(1.0f - a * a + 1e-8f) * sigmoidf_(inp);
    bp = beta * xcv;
}

__global__ void scanA_k(const float* __restrict__ gates,
                        const float* __restrict__ xc,
                        const float* __restrict__ Lambda,
                        float* __restrict__ chA, float* __restrict__ chB)
{
    int id = blockIdx.x * blockDim.x + threadIdx.x;
    if (id >= NCH * NCHUNK) return;
    int c     = id & (NCH - 1);
    int chunk = id >> 14;
    int b = c >> 9;
    int h = c & (HIDDEN - 1);
    float sp = log1pf(__expf(Lambda[h]));

    size_t tok0 = (size_t)b * SEQ + chunk * TCHUNK;
    float A = 1.0f, Bv = 0.0f;
    #pragma unroll 4
    for (int tt = 0; tt < TCHUNK; tt++) {
        size_t tok = tok0 + tt;
        float rec = gates[tok * 1024 + h];
        float inp = gates[tok * 1024 + 512 + h];
        float a, bp;
        gate_ab(rec, inp, sp, xc[tok * HIDDEN + h], a, bp);
        A *= a;
        Bv = fmaf(a, Bv, bp);
    }
    chA[id] = A;
    chB[id] = Bv;
}

__global__ void scanB_k(const float* __restrict__ chA, const float* __restrict__ chB,
                        float* __restrict__ pref)
{
    int c = blockIdx.x * blockDim.x + threadIdx.x;
    if (c >= NCH) return;
    float s = 0.0f;
    #pragma unroll
    for (int chunk = 0; chunk < NCHUNK; chunk++) {
        pref[chunk * NCH + c] = s;
        s = fmaf(chA[chunk * NCH + c], s, chB[chunk * NCH + c]);
    }
}

__global__ void scanC_k(const float* __restrict__ gates,
                        const float* __restrict__ xc,
                        const float* __restrict__ xz,
                        const float* __restrict__ Lambda,
                        const float* __restrict__ pref,
                        float* __restrict__ gh)
{
    int id = blockIdx.x * blockDim.x + threadIdx.x;
    if (id >= NCH * NCHUNK) return;
    int c     = id & (NCH - 1);
    int chunk = id >> 14;
    int b = c >> 9;
    int h = c & (HIDDEN - 1);
    float sp = log1pf(__expf(Lambda[h]));

    size_t tok0 = (size_t)b * SEQ + chunk * TCHUNK;
    float state = pref[id];
    #pragma unroll 4
    for (int tt = 0; tt < TCHUNK; tt++) {
        size_t tok = tok0 + tt;
        float rec = gates[tok * 1024 + h];
        float inp = gates[tok * 1024 + 512 + h];
        float a, bp;
        gate_ab(rec, inp, sp, xc[tok * HIDDEN + h], a, bp);
        state = fmaf(a, state, bp);
        float z = xz[tok * 1024 + 512 + h];
        gh[tok * HIDDEN + h] = state * siluf(z);
    }
}

// ---------------------------------------------------------------------------
// LayerNorm over D=256: out = LN(a + res) * gamma + beta
// ---------------------------------------------------------------------------
__global__ void ln_k(const float* __restrict__ a,
                     const float* __restrict__ res,
                     const float* __restrict__ gamma,
                     const float* __restrict__ beta,
                     float* __restrict__ out)
{
    int tok = blockIdx.x;
    int i = threadIdx.x;
    size_t off = (size_t)tok * DMODEL + i;
    float v = a[off] + res[off];

    float s = v, s2 = v * v;
    #pragma unroll
    for (int o = 16; o > 0; o >>= 1) {
        s  += __shfl_xor_sync(0xffffffffu, s,  o);
        s2 += __shfl_xor_sync(0xffffffffu, s2, o);
    }
    __shared__ float sh[2][8];
    int w = i >> 5, l = i & 31;
    if (l == 0) { sh[0][w] = s; sh[1][w] = s2; }
    __syncthreads();
    if (w == 0) {
        float ts  = (l < 8) ? sh[0][l] : 0.0f;
        float ts2 = (l < 8) ? sh[1][l] : 0.0f;
        #pragma unroll
        for (int o = 4; o > 0; o >>= 1) {
            ts  += __shfl_xor_sync(0xffffffffu, ts,  o);
            ts2 += __shfl_xor_sync(0xffffffffu, ts2, o);
        }
        if (l == 0) { sh[0][0] = ts; sh[1][0] = ts2; }
    }
    __syncthreads();
    float mean = sh[0][0] * (1.0f / DMODEL);
    float var  = sh[1][0] * (1.0f / DMODEL) - mean * mean;
    float inv  = rsqrtf(var + 1e-12f);
    out[off] = (v - mean) * inv * gamma[i] + beta[i];
}

// ---------------------------------------------------------------------------
// Host launcher
// ---------------------------------------------------------------------------
extern "C" void kernel_launch(void* const* d_in, const int* in_sizes, int n_in,
                              void* d_out, int out_size)
{
    const float* x      = (const float*)d_in[0];
    const float* w_in   = (const float*)d_in[1];
    const float* conv_w = (const float*)d_in[2];
    const float* conv_b = (const float*)d_in[3];
    const float* w_gate = (const float*)d_in[4];
    const float* b_gate = (const float*)d_in[5];
    const float* Lambda = (const float*)d_in[6];
    const float* w_out  = (const float*)d_in[7];
    const float* ln1_g  = (const float*)d_in[8];
    const float* ln1_b  = (const float*)d_in[9];
    const float* ffn_w1 = (const float*)d_in[10];
    const float* ffn_b1 = (const float*)d_in[11];
    const float* ffn_w2 = (const float*)d_in[12];
    const float* ffn_b2 = (const float*)d_in[13];
    const float* ln2_g  = (const float*)d_in[14];
    const float* ln2_b  = (const float*)d_in[15];
    float* out = (float*)d_out;

    float *xz, *xc, *gates, *gh, *y, *hs, *u, *ff, *chA, *chB, *pref;
    cudaGetSymbolAddress((void**)&xz,    g_xz);
    cudaGetSymbolAddress((void**)&xc,    g_xc);
    cudaGetSymbolAddress((void**)&gates, g_gates);
    cudaGetSymbolAddress((void**)&gh,    g_gh);
    cudaGetSymbolAddress((void**)&y,     g_y);
    cudaGetSymbolAddress((void**)&hs,    g_hs);
    cudaGetSymbolAddress((void**)&u,     g_u);
    cudaGetSymbolAddress((void**)&ff,    g_ff);
    cudaGetSymbolAddress((void**)&chA,   g_chA);
    cudaGetSymbolAddress((void**)&chB,   g_chB);
    cudaGetSymbolAddress((void**)&pref,  g_pref);

    const int M = TOKENS;
    dim3 thr(256);

    // 1) xz = x @ w_in
    tc_gemm<0><<<dim3(1024 / BN, M / BM), thr>>>(x, w_in, nullptr, xz, M, 1024, DMODEL);

    // 2) conv + silu
    conv_silu_k<<<(TOKENS * (HIDDEN / 4)) / 256, thr>>>(xz, conv_w, conv_b, xc);

    // 3) gates = xc @ w_gates + b_gates
    tc_gemm<1><<<dim3(1024 / BN, M / BM), thr>>>(xc, w_gate, b_gate, gates, M, 1024, HIDDEN);

    // 4-6) chunked scan (gate nonlinearity fused)
    scanA_k<<<(NCH * NCHUNK) / 256, thr>>>(gates, xc, Lambda, chA, chB);
    scanB_k<<<NCH / 256, thr>>>(chA, chB, pref);
    scanC_k<<<(NCH * NCHUNK) / 256, thr>>>(gates, xc, xz, Lambda, pref, gh);

    // 7) y = gh @ w_out
    tc_gemm<0><<<dim3(DMODEL / BN, M / BM), thr>>>(gh, w_out, nullptr, y, M, DMODEL, HIDDEN);

    // 8) hs = LN1(y + x)
    ln_k<<<TOKENS, DMODEL>>>(y, x, ln1_g, ln1_b, hs);

    // 9) u = silu(hs @ ffn_w1 + b1)
    tc_gemm<2><<<dim3(INNER / BN, M / BM), thr>>>(hs, ffn_w1, ffn_b1, u, M, INNER, DMODEL);

    // 10) ff = u @ ffn_w2 + b2
    tc_gemm<1><<<dim3(DMODEL / BN, M / BM), thr>>>(u, ffn_w2, ffn_b2, ff, M, DMODEL, INNER);

    // 11) out = LN2(ff + hs)
    ln_k<<<TOKENS, DMODEL>>>(ff, hs, ln2_g, ln2_b, out);
}

// round 4
// speedup vs baseline: 3.7410x; 1.3016x over previous
#include <cuda_runtime.h>
#include <cuda_fp16.h>
#include <math.h>
#include <stdint.h>

// Problem constants
#define BATCH   32
#define SEQ     2048
#define DMODEL  256
#define HIDDEN  512
#define INNER   1024
#define TOKENS  (BATCH * SEQ)           // 65536
#define NCH     (BATCH * HIDDEN)        // 16384 scan channels
#define NCHUNK  16
#define TCHUNK  (SEQ / NCHUNK)          // 128

// ---------------------------------------------------------------------------
// Scratch (static device memory)
// ---------------------------------------------------------------------------
__device__ float  g_xz   [(size_t)TOKENS * 1024];   // [xh | z] fp32
__device__ float  g_xc   [(size_t)TOKENS * HIDDEN]; // fp32 (scan)
__device__ __half g_xc16 [(size_t)TOKENS * HIDDEN]; // fp16 (GEMM input)
__device__ __half g_x16  [(size_t)TOKENS * DMODEL];
__device__ __half g_gates16[(size_t)TOKENS * 1024];
__device__ __half g_gh16 [(size_t)TOKENS * HIDDEN];
__device__ float  g_y    [(size_t)TOKENS * DMODEL];
__device__ float  g_hs   [(size_t)TOKENS * DMODEL];
__device__ __half g_hs16 [(size_t)TOKENS * DMODEL];
__device__ __half g_u16  [(size_t)TOKENS * INNER];
__device__ float  g_ff   [(size_t)TOKENS * DMODEL];
__device__ float  g_chA  [(size_t)NCH * NCHUNK];
__device__ float  g_chB  [(size_t)NCH * NCHUNK];
__device__ float  g_pref [(size_t)NCH * NCHUNK];
// transposed fp16 weights [N, K]
__device__ __half g_wt_in   [1024 * 256];
__device__ __half g_wt_gates[1024 * 512];
__device__ __half g_wt_out  [256 * 512];
__device__ __half g_wt_f1   [1024 * 256];
__device__ __half g_wt_f2   [256 * 1024];

__device__ __forceinline__ float siluf(float v)     { return v / (1.0f + __expf(-v)); }
__device__ __forceinline__ float sigmoidf_(float v) { return 1.0f / (1.0f + __expf(-v)); }

// ---------------------------------------------------------------------------
// cp.async helpers
// ---------------------------------------------------------------------------
__device__ __forceinline__ void cp_async16(void* smem, const void* gmem) {
    unsigned s = (unsigned)__cvta_generic_to_shared(smem);
    asm volatile("cp.async.cg.shared.global [%0], [%1], 16;" :: "r"(s), "l"(gmem));
}
__device__ __forceinline__ void cp_commit() { asm volatile("cp.async.commit_group;"); }
template<int N> __device__ __forceinline__ void cp_wait() {
    asm volatile("cp.async.wait_group %0;" :: "n"(N));
}

__device__ __forceinline__ void mma_f16(float c[4], const uint32_t a[4], const uint32_t b[2]) {
    asm volatile(
        "mma.sync.aligned.m16n8k16.row.col.f32.f16.f16.f32 "
        "{%0,%1,%2,%3}, {%4,%5,%6,%7}, {%8,%9}, {%0,%1,%2,%3};\n"
        : "+f"(c[0]), "+f"(c[1]), "+f"(c[2]), "+f"(c[3])
        : "r"(a[0]), "r"(a[1]), "r"(a[2]), "r"(a[3]), "r"(b[0]), "r"(b[1]));
}

// ---------------------------------------------------------------------------
// fp16 tensor-core GEMM: C[M,N] = A[M,K] @ Bt[N,K]^T  (A,Bt fp16, acc fp32)
// 128x128 block tile, BK=32, 256 threads, 8 warps (2x4), warp tile 64x32.
// Smem rows padded to 80B (40 fp16): conflict-free direct LDS frag loads.
// EPI: 0=store fp32, 1=+bias fp32, 2=silu(+bias)->fp16, 3=+bias->fp16
// ---------------------------------------------------------------------------
#define HBK 32
#define SROWB 80   // bytes per smem row (64 data + 16 pad)

template<int EPI>
__global__ void __launch_bounds__(256) hgemm(
    const __half* __restrict__ A, const __half* __restrict__ Bt,
    const float* __restrict__ bias,
    float* __restrict__ C, __half* __restrict__ Ch,
    int M, int N, int K)
{
    __shared__ __align__(16) unsigned char As_[2][128 * SROWB];
    __shared__ __align__(16) unsigned char Bs_[2][128 * SROWB];

    const int tid  = threadIdx.x;
    const int warp = tid >> 5;
    const int lane = tid & 31;
    const int g    = lane >> 2;   // 0..7
    const int tg   = lane & 3;    // 0..3

    const int bm = blockIdx.y * 128;
    const int bn = blockIdx.x * 128;
    const int wm = (warp >> 2) * 64;
    const int wn = (warp & 3) * 32;

    // load mapping: row = tid>>1 (0..127), seg = tid&1 (32B each)
    const int lrow = tid >> 1;
    const int lseg = (tid & 1) * 32;      // byte offset within 64B row

    float acc[4][4][4];
    #pragma unroll
    for (int mi = 0; mi < 4; mi++)
        #pragma unroll
        for (int ni = 0; ni < 4; ni++)
            #pragma unroll
            for (int r = 0; r < 4; r++) acc[mi][ni][r] = 0.0f;

    const int KT = K / HBK;
    const __half* Ag = A  + (size_t)(bm + lrow) * K + (lseg >> 1);
    const __half* Bg = Bt + (size_t)(bn + lrow) * K + (lseg >> 1);

    auto load_tile = [&](int kt, int buf) {
        const __half* a = Ag + kt * HBK;
        const __half* b = Bg + kt * HBK;
        unsigned char* as = As_[buf] + lrow * SROWB + lseg;
        unsigned char* bs = Bs_[buf] + lrow * SROWB + lseg;
        cp_async16(as,      a);
        cp_async16(as + 16, a + 8);
        cp_async16(bs,      b);
        cp_async16(bs + 16, b + 8);
        cp_commit();
    };

    load_tile(0, 0);

    for (int kt = 0; kt < KT; kt++) {
        const int buf = kt & 1;
        if (kt + 1 < KT) {
            load_tile(kt + 1, buf ^ 1);
            cp_wait<1>();
        } else {
            cp_wait<0>();
        }
        __syncthreads();

        const unsigned char* as = As_[buf];
        const unsigned char* bs = Bs_[buf];
        #pragma unroll
        for (int ks = 0; ks < 2; ks++) {
            const int kb = ks * 32 + tg * 4;   // byte offset of k pair
            uint32_t af[4][4];
            #pragma unroll
            for (int mi = 0; mi < 4; mi++) {
                const int r0 = wm + mi * 16 + g;
                const unsigned char* p = as + r0 * SROWB + kb;
                af[mi][0] = *reinterpret_cast<const uint32_t*>(p);
                af[mi][1] = *reinterpret_cast<const uint32_t*>(p + 8 * SROWB);
                af[mi][2] = *reinterpret_cast<const uint32_t*>(p + 16);
                af[mi][3] = *reinterpret_cast<const uint32_t*>(p + 8 * SROWB + 16);
            }
            uint32_t bf[4][2];
            #pragma unroll
            for (int ni = 0; ni < 4; ni++) {
                const int r0 = wn + ni * 8 + g;
                const unsigned char* p = bs + r0 * SROWB + kb;
                bf[ni][0] = *reinterpret_cast<const uint32_t*>(p);
                bf[ni][1] = *reinterpret_cast<const uint32_t*>(p + 16);
            }
            #pragma unroll
            for (int mi = 0; mi < 4; mi++)
                #pragma unroll
                for (int ni = 0; ni < 4; ni++)
                    mma_f16(acc[mi][ni], af[mi], bf[ni]);
        }
        __syncthreads();
    }

    // epilogue
    #pragma unroll
    for (int mi = 0; mi < 4; mi++) {
        const int r0 = bm + wm + mi * 16 + g;
        #pragma unroll
        for (int ni = 0; ni < 4; ni++) {
            const int col = bn + wn + ni * 8 + tg * 2;
            float b0 = 0.f, b1 = 0.f;
            if (EPI >= 1) { b0 = bias[col]; b1 = bias[col + 1]; }
            float v0 = acc[mi][ni][0] + b0;
            float v1 = acc[mi][ni][1] + b1;
            float v2 = acc[mi][ni][2] + b0;
            float v3 = acc[mi][ni][3] + b1;
            if (EPI == 2) { v0 = siluf(v0); v1 = siluf(v1); v2 = siluf(v2); v3 = siluf(v3); }
            if (EPI <= 1) {
                *reinterpret_cast<float2*>(C + (size_t)r0 * N + col)       = make_float2(v0, v1);
                *reinterpret_cast<float2*>(C + (size_t)(r0 + 8) * N + col) = make_float2(v2, v3);
            } else {
                *reinterpret_cast<__half2*>(Ch + (size_t)r0 * N + col)       = __floats2half2_rn(v0, v1);
                *reinterpret_cast<__half2*>(Ch + (size_t)(r0 + 8) * N + col) = __floats2half2_rn(v2, v3);
            }
        }
    }
}

// ---------------------------------------------------------------------------
// Weight transpose + fp32->fp16: out[C,R] = (half)in[R,C]
// ---------------------------------------------------------------------------
__global__ void transpose_cvt_k(const float* __restrict__ in, __half* __restrict__ out,
                                int R, int C)
{
    __shared__ float t[32][33];
    const int c0 = blockIdx.x * 32, r0 = blockIdx.y * 32;
    const int x = threadIdx.x, y = threadIdx.y;
    #pragma unroll
    for (int i = 0; i < 32; i += 8)
        t[y + i][x] = in[(size_t)(r0 + y + i) * C + c0 + x];
    __syncthreads();
    #pragma unroll
    for (int i = 0; i < 32; i += 8)
        out[(size_t)(c0 + y + i) * R + r0 + x] = __float2half(t[x][y + i]);
}

// x fp32 -> fp16
__global__ void cvt_x_k(const float* __restrict__ in, __half* __restrict__ out, int n4)
{
    int i = blockIdx.x * blockDim.x + threadIdx.x;
    if (i >= n4) return;
    float4 v = reinterpret_cast<const float4*>(in)[i];
    __half2 lo = __floats2half2_rn(v.x, v.y);
    __half2 hi = __floats2half2_rn(v.z, v.w);
    reinterpret_cast<uint2*>(out)[i] =
        make_uint2(*reinterpret_cast<uint32_t*>(&lo), *reinterpret_cast<uint32_t*>(&hi));
}

// ---------------------------------------------------------------------------
// Depthwise causal conv (K=4) + SiLU; writes xc fp32 and xc16 fp16
// ---------------------------------------------------------------------------
__global__ void conv_silu_k(const float* __restrict__ xz,
                            const float* __restrict__ cw,
                            const float* __restrict__ cb,
                            float* __restrict__ xc,
                            __half* __restrict__ xc16)
{
    int idx = blockIdx.x * blockDim.x + threadIdx.x;
    if (idx >= TOKENS * (HIDDEN / 4)) return;
    int h4  = idx & 127;
    int tok = idx >> 7;
    int t   = tok & (SEQ - 1);
    int h   = h4 * 4;

    const float* row = xz + (size_t)tok * 1024 + h;
    float4 c0 = *reinterpret_cast<const float4*>(row);
    float4 c1 = (t >= 1) ? *reinterpret_cast<const float4*>(row - 1024) : make_float4(0,0,0,0);
    float4 c2 = (t >= 2) ? *reinterpret_cast<const float4*>(row - 2048) : make_float4(0,0,0,0);
    float4 c3 = (t >= 3) ? *reinterpret_cast<const float4*>(row - 3072) : make_float4(0,0,0,0);

    float4 o;
    float4 bb = *reinterpret_cast<const float4*>(cb + h);
    {
        float4 w = *reinterpret_cast<const float4*>(cw + (size_t)(h + 0) * 4);
        o.x = siluf(fmaf(w.w, c0.x, fmaf(w.z, c1.x, fmaf(w.y, c2.x, fmaf(w.x, c3.x, bb.x)))));
    }
    {
        float4 w = *reinterpret_cast<const float4*>(cw + (size_t)(h + 1) * 4);
        o.y = siluf(fmaf(w.w, c0.y, fmaf(w.z, c1.y, fmaf(w.y, c2.y, fmaf(w.x, c3.y, bb.y)))));
    }
    {
        float4 w = *reinterpret_cast<const float4*>(cw + (size_t)(h + 2) * 4);
        o.z = siluf(fmaf(w.w, c0.z, fmaf(w.z, c1.z, fmaf(w.y, c2.z, fmaf(w.x, c3.z, bb.z)))));
    }
    {
        float4 w = *reinterpret_cast<const float4*>(cw + (size_t)(h + 3) * 4);
        o.w = siluf(fmaf(w.w, c0.w, fmaf(w.z, c1.w, fmaf(w.y, c2.w, fmaf(w.x, c3.w, bb.w)))));
    }
    *reinterpret_cast<float4*>(xc + (size_t)tok * HIDDEN + h) = o;
    __half2 lo = __floats2half2_rn(o.x, o.y);
    __half2 hi = __floats2half2_rn(o.z, o.w);
    *reinterpret_cast<uint2*>(xc16 + (size_t)tok * HIDDEN + h) =
        make_uint2(*reinterpret_cast<uint32_t*>(&lo), *reinterpret_cast<uint32_t*>(&hi));
}

// ---------------------------------------------------------------------------
// Chunked scan (gate nonlinearity fused); gates in fp16
// ---------------------------------------------------------------------------
__device__ __forceinline__ void gate_ab(float rec, float inp, float sp, float xcv,
                                        float& a, float& bp)
{
    a = __expf(-sp * sigmoidf_(rec));
    float beta = sqrtf(1.0f - a * a + 1e-8f) * sigmoidf_(inp);
    bp = beta * xcv;
}

__global__ void scanA_k(const __half* __restrict__ gates,
                        const float* __restrict__ xc,
                        const float* __restrict__ Lambda,
                        float* __restrict__ chA, float* __restrict__ chB)
{
    int id = blockIdx.x * blockDim.x + threadIdx.x;
    if (id >= NCH * NCHUNK) return;
    int c     = id & (NCH - 1);
    int chunk = id >> 14;
    int b = c >> 9;
    int h = c & (HIDDEN - 1);
    float sp = log1pf(__expf(Lambda[h]));

    size_t tok0 = (size_t)b * SEQ + chunk * TCHUNK;
    float A = 1.0f, Bv = 0.0f;
    #pragma unroll 4
    for (int tt = 0; tt < TCHUNK; tt++) {
        size_t tok = tok0 + tt;
        float rec = __half2float(gates[tok * 1024 + h]);
        float inp = __half2float(gates[tok * 1024 + 512 + h]);
        float a, bp;
        gate_ab(rec, inp, sp, xc[tok * HIDDEN + h], a, bp);
        A *= a;
        Bv = fmaf(a, Bv, bp);
    }
    chA[id] = A;
    chB[id] = Bv;
}

__global__ void scanB_k(const float* __restrict__ chA, const float* __restrict__ chB,
                        float* __restrict__ pref)
{
    int c = blockIdx.x * blockDim.x + threadIdx.x;
    if (c >= NCH) return;
    float s = 0.0f;
    #pragma unroll
    for (int chunk = 0; chunk < NCHUNK; chunk++) {
        pref[chunk * NCH + c] = s;
        s = fmaf(chA[chunk * NCH + c], s, chB[chunk * NCH + c]);
    }
}

__global__ void scanC_k(const __half* __restrict__ gates,
                        const float* __restrict__ xc,
                        const float* __restrict__ xz,
                        const float* __restrict__ Lambda,
                        const float* __restrict__ pref,
                        __half* __restrict__ gh16)
{
    int id = blockIdx.x * blockDim.x + threadIdx.x;
    if (id >= NCH * NCHUNK) return;
    int c     = id & (NCH - 1);
    int chunk = id >> 14;
    int b = c >> 9;
    int h = c & (HIDDEN - 1);
    float sp = log1pf(__expf(Lambda[h]));

    size_t tok0 = (size_t)b * SEQ + chunk * TCHUNK;
    float state = pref[id];
    #pragma unroll 4
    for (int tt = 0; tt < TCHUNK; tt++) {
        size_t tok = tok0 + tt;
        float rec = __half2float(gates[tok * 1024 + h]);
        float inp = __half2float(gates[tok * 1024 + 512 + h]);
        float a, bp;
        gate_ab(rec, inp, sp, xc[tok * HIDDEN + h], a, bp);
        state = fmaf(a, state, bp);
        float z = xz[tok * 1024 + 512 + h];
        gh16[tok * HIDDEN + h] = __float2half(state * siluf(z));
    }
}

// ---------------------------------------------------------------------------
// LayerNorm over D=256: out = LN(a + res) * gamma + beta (+ optional fp16 copy)
// ---------------------------------------------------------------------------
template<bool H16>
__global__ void ln_k(const float* __restrict__ a,
                     const float* __restrict__ res,
                     const float* __restrict__ gamma,
                     const float* __restrict__ beta,
                     float* __restrict__ out,
                     __half* __restrict__ out16)
{
    int tok = blockIdx.x;
    int i = threadIdx.x;
    size_t off = (size_t)tok * DMODEL + i;
    float v = a[off] + res[off];

    float s = v, s2 = v * v;
    #pragma unroll
    for (int o = 16; o > 0; o >>= 1) {
        s  += __shfl_xor_sync(0xffffffffu, s,  o);
        s2 += __shfl_xor_sync(0xffffffffu, s2, o);
    }
    __shared__ float sh[2][8];
    int w = i >> 5, l = i & 31;
    if (l == 0) { sh[0][w] = s; sh[1][w] = s2; }
    __syncthreads();
    if (w == 0) {
        float ts  = (l < 8) ? sh[0][l] : 0.0f;
        float ts2 = (l < 8) ? sh[1][l] : 0.0f;
        #pragma unroll
        for (int o = 4; o > 0; o >>= 1) {
            ts  += __shfl_xor_sync(0xffffffffu, ts,  o);
            ts2 += __shfl_xor_sync(0xffffffffu, ts2, o);
        }
        if (l == 0) { sh[0][0] = ts; sh[1][0] = ts2; }
    }
    __syncthreads();
    float mean = sh[0][0] * (1.0f / DMODEL);
    float var  = sh[1][0] * (1.0f / DMODEL) - mean * mean;
    float inv  = rsqrtf(var + 1e-12f);
    float o = (v - mean) * inv * gamma[i] + beta[i];
    out[off] = o;
    if (H16) out16[off] = __float2half(o);
}

// ---------------------------------------------------------------------------
// Host launcher
// ---------------------------------------------------------------------------
extern "C" void kernel_launch(void* const* d_in, const int* in_sizes, int n_in,
                              void* d_out, int out_size)
{
    const float* x      = (const float*)d_in[0];
    const float* w_in   = (const float*)d_in[1];
    const float* conv_w = (const float*)d_in[2];
    const float* conv_b = (const float*)d_in[3];
    const float* w_gate = (const float*)d_in[4];
    const float* b_gate = (const float*)d_in[5];
    const float* Lambda = (const float*)d_in[6];
    const float* w_out  = (const float*)d_in[7];
    const float* ln1_g  = (const float*)d_in[8];
    const float* ln1_b  = (const float*)d_in[9];
    const float* ffn_w1 = (const float*)d_in[10];
    const float* ffn_b1 = (const float*)d_in[11];
    const float* ffn_w2 = (const float*)d_in[12];
    const float* ffn_b2 = (const float*)d_in[13];
    const float* ln2_g  = (const float*)d_in[14];
    const float* ln2_b  = (const float*)d_in[15];
    float* out = (float*)d_out;

    float  *xz, *xc, *y, *hs, *ff, *chA, *chB, *pref;
    __half *x16, *xc16, *gates16, *gh16, *hs16, *u16;
    __half *wt_in, *wt_gates, *wt_out, *wt_f1, *wt_f2;
    cudaGetSymbolAddress((void**)&xz,      g_xz);
    cudaGetSymbolAddress((void**)&xc,      g_xc);
    cudaGetSymbolAddress((void**)&xc16,    g_xc16);
    cudaGetSymbolAddress((void**)&x16,     g_x16);
    cudaGetSymbolAddress((void**)&gates16, g_gates16);
    cudaGetSymbolAddress((void**)&gh16,    g_gh16);
    cudaGetSymbolAddress((void**)&y,       g_y);
    cudaGetSymbolAddress((void**)&hs,      g_hs);
    cudaGetSymbolAddress((void**)&hs16,    g_hs16);
    cudaGetSymbolAddress((void**)&u16,     g_u16);
    cudaGetSymbolAddress((void**)&ff,      g_ff);
    cudaGetSymbolAddress((void**)&chA,     g_chA);
    cudaGetSymbolAddress((void**)&chB,     g_chB);
    cudaGetSymbolAddress((void**)&pref,    g_pref);
    cudaGetSymbolAddress((void**)&wt_in,    g_wt_in);
    cudaGetSymbolAddress((void**)&wt_gates, g_wt_gates);
    cudaGetSymbolAddress((void**)&wt_out,   g_wt_out);
    cudaGetSymbolAddress((void**)&wt_f1,    g_wt_f1);
    cudaGetSymbolAddress((void**)&wt_f2,    g_wt_f2);

    const int M = TOKENS;
    dim3 tb(32, 8);

    // 0) weight transpose+convert, x convert
    transpose_cvt_k<<<dim3(1024/32, 256/32),  tb>>>(w_in,   wt_in,    256, 1024);
    transpose_cvt_k<<<dim3(1024/32, 512/32),  tb>>>(w_gate, wt_gates, 512, 1024);
    transpose_cvt_k<<<dim3(256/32,  512/32),  tb>>>(w_out,  wt_out,   512, 256);
    transpose_cvt_k<<<dim3(1024/32, 256/32),  tb>>>(ffn_w1, wt_f1,    256, 1024);
    transpose_cvt_k<<<dim3(256/32, 1024/32),  tb>>>(ffn_w2, wt_f2,   1024, 256);
    cvt_x_k<<<(TOKENS * DMODEL / 4 + 255) / 256, 256>>>(x, x16, TOKENS * DMODEL / 4);

    // 1) xz = x @ w_in            (fp32 out)
    hgemm<0><<<dim3(1024/128, M/128), 256>>>(x16, wt_in, nullptr, xz, nullptr, M, 1024, 256);

    // 2) conv + silu -> xc, xc16
    conv_silu_k<<<(TOKENS * (HIDDEN/4)) / 256, 256>>>(xz, conv_w, conv_b, xc, xc16);

    // 3) gates16 = xc @ w_gates + b_gates   (fp16 out)
    hgemm<3><<<dim3(1024/128, M/128), 256>>>(xc16, wt_gates, b_gate, nullptr, gates16, M, 1024, 512);

    // 4-6) chunked scan -> gh16
    scanA_k<<<(NCH * NCHUNK) / 256, 256>>>(gates16, xc, Lambda, chA, chB);
    scanB_k<<<NCH / 256, 256>>>(chA, chB, pref);
    scanC_k<<<(NCH * NCHUNK) / 256, 256>>>(gates16, xc, xz, Lambda, pref, gh16);

    // 7) y = gh @ w_out           (fp32 out)
    hgemm<0><<<dim3(256/128, M/128), 256>>>(gh16, wt_out, nullptr, y, nullptr, M, 256, 512);

    // 8) hs = LN1(y + x), + fp16 copy
    ln_k<true><<<TOKENS, DMODEL>>>(y, x, ln1_g, ln1_b, hs, hs16);

    // 9) u16 = silu(hs @ ffn_w1 + b1)   (fp16 out)
    hgemm<2><<<dim3(1024/128, M/128), 256>>>(hs16, wt_f1, ffn_b1, nullptr, u16, M, 1024, 256);

    // 10) ff = u @ ffn_w2 + b2    (fp32 out)
    hgemm<1><<<dim3(256/128, M/128), 256>>>(u16, wt_f2, ffn_b2, ff, nullptr, M, 256, 1024);

    // 11) out = LN2(ff + hs)
    ln_k<false><<<TOKENS, DMODEL>>>(ff, hs, ln2_g, ln2_b, out, nullptr);
}

// round 5
// speedup vs baseline: 3.7443x; 1.0009x over previous
#include <cuda_runtime.h>
#include <cuda_fp16.h>
#include <math.h>
#include <stdint.h>

// Problem constants
#define BATCH   32
#define SEQ     2048
#define DMODEL  256
#define HIDDEN  512
#define INNER   1024
#define TOKENS  (BATCH * SEQ)           // 65536
#define NCH     (BATCH * HIDDEN)        // 16384 scan channels
#define NCHUNK  16
#define TCHUNK  (SEQ / NCHUNK)          // 128

// ---------------------------------------------------------------------------
// Scratch (static device memory)
// ---------------------------------------------------------------------------
__device__ float  g_xz   [(size_t)TOKENS * 1024];   // [xh | z] fp32
__device__ float  g_xc   [(size_t)TOKENS * HIDDEN]; // fp32 (scan)
__device__ __half g_xc16 [(size_t)TOKENS * HIDDEN]; // fp16 (GEMM input)
__device__ __half g_x16  [(size_t)TOKENS * DMODEL];
__device__ __half g_gates16[(size_t)TOKENS * 1024];
__device__ __half g_gh16 [(size_t)TOKENS * HIDDEN];
__device__ float  g_y    [(size_t)TOKENS * DMODEL];
__device__ float  g_hs   [(size_t)TOKENS * DMODEL];
__device__ __half g_hs16 [(size_t)TOKENS * DMODEL];
__device__ __half g_u16  [(size_t)TOKENS * INNER];
__device__ float  g_ff   [(size_t)TOKENS * DMODEL];
__device__ float  g_chA  [(size_t)NCH * NCHUNK];
__device__ float  g_chB  [(size_t)NCH * NCHUNK];
__device__ float  g_pref [(size_t)NCH * NCHUNK];
// transposed fp16 weights [N, K]
__device__ __half g_wt_in   [1024 * 256];
__device__ __half g_wt_gates[1024 * 512];
__device__ __half g_wt_out  [256 * 512];
__device__ __half g_wt_f1   [1024 * 256];
__device__ __half g_wt_f2   [256 * 1024];

__device__ __forceinline__ float siluf(float v)     { return v / (1.0f + __expf(-v)); }
__device__ __forceinline__ float sigmoidf_(float v) { return 1.0f / (1.0f + __expf(-v)); }

// ---------------------------------------------------------------------------
// cp.async helpers
// ---------------------------------------------------------------------------
__device__ __forceinline__ void cp_async16(void* smem, const void* gmem) {
    unsigned s = (unsigned)__cvta_generic_to_shared(smem);
    asm volatile("cp.async.cg.shared.global [%0], [%1], 16;" :: "r"(s), "l"(gmem));
}
__device__ __forceinline__ void cp_commit() { asm volatile("cp.async.commit_group;"); }
template<int N> __device__ __forceinline__ void cp_wait() {
    asm volatile("cp.async.wait_group %0;" :: "n"(N));
}

__device__ __forceinline__ void mma_f16(float c[4], const uint32_t a[4], const uint32_t b[2]) {
    asm volatile(
        "mma.sync.aligned.m16n8k16.row.col.f32.f16.f16.f32 "
        "{%0,%1,%2,%3}, {%4,%5,%6,%7}, {%8,%9}, {%0,%1,%2,%3};\n"
        : "+f"(c[0]), "+f"(c[1]), "+f"(c[2]), "+f"(c[3])
        : "r"(a[0]), "r"(a[1]), "r"(a[2]), "r"(a[3]), "r"(b[0]), "r"(b[1]));
}

// ---------------------------------------------------------------------------
// fp16 tensor-core GEMM: C[M,N] = A[M,K] @ Bt[N,K]^T  (A,Bt fp16, acc fp32)
// 128x128 block tile, BK=32, 256 threads, 8 warps (2x4), warp tile 64x32.
// Smem rows padded to 80B (40 fp16): conflict-free direct LDS frag loads.
// EPI: 0=store fp32, 1=+bias fp32, 2=silu(+bias)->fp16, 3=+bias->fp16
// ---------------------------------------------------------------------------
#define HBK 32
#define SROWB 80   // bytes per smem row (64 data + 16 pad)

template<int EPI>
__global__ void __launch_bounds__(256) hgemm(
    const __half* __restrict__ A, const __half* __restrict__ Bt,
    const float* __restrict__ bias,
    float* __restrict__ C, __half* __restrict__ Ch,
    int M, int N, int K)
{
    __shared__ __align__(16) unsigned char As_[2][128 * SROWB];
    __shared__ __align__(16) unsigned char Bs_[2][128 * SROWB];

    const int tid  = threadIdx.x;
    const int warp = tid >> 5;
    const int lane = tid & 31;
    const int g    = lane >> 2;   // 0..7
    const int tg   = lane & 3;    // 0..3

    const int bm = blockIdx.y * 128;
    const int bn = blockIdx.x * 128;
    const int wm = (warp >> 2) * 64;
    const int wn = (warp & 3) * 32;

    // load mapping: row = tid>>1 (0..127), seg = tid&1 (32B each)
    const int lrow = tid >> 1;
    const int lseg = (tid & 1) * 32;      // byte offset within 64B row

    float acc[4][4][4];
    #pragma unroll
    for (int mi = 0; mi < 4; mi++)
        #pragma unroll
        for (int ni = 0; ni < 4; ni++)
            #pragma unroll
            for (int r = 0; r < 4; r++) acc[mi][ni][r] = 0.0f;

    const int KT = K / HBK;
    const __half* Ag = A  + (size_t)(bm + lrow) * K + (lseg >> 1);
    const __half* Bg = Bt + (size_t)(bn + lrow) * K + (lseg >> 1);

    auto load_tile = [&](int kt, int buf) {
        const __half* a = Ag + kt * HBK;
        const __half* b = Bg + kt * HBK;
        unsigned char* as = As_[buf] + lrow * SROWB + lseg;
        unsigned char* bs = Bs_[buf] + lrow * SROWB + lseg;
        cp_async16(as,      a);
        cp_async16(as + 16, a + 8);
        cp_async16(bs,      b);
        cp_async16(bs + 16, b + 8);
        cp_commit();
    };

    load_tile(0, 0);

    for (int kt = 0; kt < KT; kt++) {
        const int buf = kt & 1;
        if (kt + 1 < KT) {
            load_tile(kt + 1, buf ^ 1);
            cp_wait<1>();
        } else {
            cp_wait<0>();
        }
        __syncthreads();

        const unsigned char* as = As_[buf];
        const unsigned char* bs = Bs_[buf];
        #pragma unroll
        for (int ks = 0; ks < 2; ks++) {
            const int kb = ks * 32 + tg * 4;   // byte offset of k pair
            uint32_t af[4][4];
            #pragma unroll
            for (int mi = 0; mi < 4; mi++) {
                const int r0 = wm + mi * 16 + g;
                const unsigned char* p = as + r0 * SROWB + kb;
                af[mi][0] = *reinterpret_cast<const uint32_t*>(p);
                af[mi][1] = *reinterpret_cast<const uint32_t*>(p + 8 * SROWB);
                af[mi][2] = *reinterpret_cast<const uint32_t*>(p + 16);
                af[mi][3] = *reinterpret_cast<const uint32_t*>(p + 8 * SROWB + 16);
            }
            uint32_t bf[4][2];
            #pragma unroll
            for (int ni = 0; ni < 4; ni++) {
                const int r0 = wn + ni * 8 + g;
                const unsigned char* p = bs + r0 * SROWB + kb;
                bf[ni][0] = *reinterpret_cast<const uint32_t*>(p);
                bf[ni][1] = *reinterpret_cast<const uint32_t*>(p + 16);
            }
            #pragma unroll
            for (int mi = 0; mi < 4; mi++)
                #pragma unroll
                for (int ni = 0; ni < 4; ni++)
                    mma_f16(acc[mi][ni], af[mi], bf[ni]);
        }
        __syncthreads();
    }

    // epilogue
    #pragma unroll
    for (int mi = 0; mi < 4; mi++) {
        const int r0 = bm + wm + mi * 16 + g;
        #pragma unroll
        for (int ni = 0; ni < 4; ni++) {
            const int col = bn + wn + ni * 8 + tg * 2;
            float b0 = 0.f, b1 = 0.f;
            if (EPI >= 1) { b0 = bias[col]; b1 = bias[col + 1]; }
            float v0 = acc[mi][ni][0] + b0;
            float v1 = acc[mi][ni][1] + b1;
            float v2 = acc[mi][ni][2] + b0;
            float v3 = acc[mi][ni][3] + b1;
            if (EPI == 2) { v0 = siluf(v0); v1 = siluf(v1); v2 = siluf(v2); v3 = siluf(v3); }
            if (EPI <= 1) {
                *reinterpret_cast<float2*>(C + (size_t)r0 * N + col)       = make_float2(v0, v1);
                *reinterpret_cast<float2*>(C + (size_t)(r0 + 8) * N + col) = make_float2(v2, v3);
            } else {
                *reinterpret_cast<__half2*>(Ch + (size_t)r0 * N + col)       = __floats2half2_rn(v0, v1);
                *reinterpret_cast<__half2*>(Ch + (size_t)(r0 + 8) * N + col) = __floats2half2_rn(v2, v3);
            }
        }
    }
}

// ---------------------------------------------------------------------------
// Weight transpose + fp32->fp16: out[C,R] = (half)in[R,C]
// ---------------------------------------------------------------------------
__global__ void transpose_cvt_k(const float* __restrict__ in, __half* __restrict__ out,
                                int R, int C)
{
    __shared__ float t[32][33];
    const int c0 = blockIdx.x * 32, r0 = blockIdx.y * 32;
    const int x = threadIdx.x, y = threadIdx.y;
    #pragma unroll
    for (int i = 0; i < 32; i += 8)
        t[y + i][x] = in[(size_t)(r0 + y + i) * C + c0 + x];
    __syncthreads();
    #pragma unroll
    for (int i = 0; i < 32; i += 8)
        out[(size_t)(c0 + y + i) * R + r0 + x] = __float2half(t[x][y + i]);
}

// x fp32 -> fp16
__global__ void cvt_x_k(const float* __restrict__ in, __half* __restrict__ out, int n4)
{
    int i = blockIdx.x * blockDim.x + threadIdx.x;
    if (i >= n4) return;
    float4 v = reinterpret_cast<const float4*>(in)[i];
    __half2 lo = __floats2half2_rn(v.x, v.y);
    __half2 hi = __floats2half2_rn(v.z, v.w);
    reinterpret_cast<uint2*>(out)[i] =
        make_uint2(*reinterpret_cast<uint32_t*>(&lo), *reinterpret_cast<uint32_t*>(&hi));
}

// ---------------------------------------------------------------------------
// Depthwise causal conv (K=4) + SiLU; writes xc fp32 and xc16 fp16
// ---------------------------------------------------------------------------
__global__ void conv_silu_k(const float* __restrict__ xz,
                            const float* __restrict__ cw,
                            const float* __restrict__ cb,
                            float* __restrict__ xc,
                            __half* __restrict__ xc16)
{
    int idx = blockIdx.x * blockDim.x + threadIdx.x;
    if (idx >= TOKENS * (HIDDEN / 4)) return;
    int h4  = idx & 127;
    int tok = idx >> 7;
    int t   = tok & (SEQ - 1);
    int h   = h4 * 4;

    const float* row = xz + (size_t)tok * 1024 + h;
    float4 c0 = *reinterpret_cast<const float4*>(row);
    float4 c1 = (t >= 1) ? *reinterpret_cast<const float4*>(row - 1024) : make_float4(0,0,0,0);
    float4 c2 = (t >= 2) ? *reinterpret_cast<const float4*>(row - 2048) : make_float4(0,0,0,0);
    float4 c3 = (t >= 3) ? *reinterpret_cast<const float4*>(row - 3072) : make_float4(0,0,0,0);

    float4 o;
    float4 bb = *reinterpret_cast<const float4*>(cb + h);
    {
        float4 w = *reinterpret_cast<const float4*>(cw + (size_t)(h + 0) * 4);
        o.x = siluf(fmaf(w.w, c0.x, fmaf(w.z, c1.x, fmaf(w.y, c2.x, fmaf(w.x, c3.x, bb.x)))));
    }
    {
        float4 w = *reinterpret_cast<const float4*>(cw + (size_t)(h + 1) * 4);
        o.y = siluf(fmaf(w.w, c0.y, fmaf(w.z, c1.y, fmaf(w.y, c2.y, fmaf(w.x, c3.y, bb.y)))));
    }
    {
        float4 w = *reinterpret_cast<const float4*>(cw + (size_t)(h + 2) * 4);
        o.z = siluf(fmaf(w.w, c0.z, fmaf(w.z, c1.z, fmaf(w.y, c2.z, fmaf(w.x, c3.z, bb.z)))));
    }
    {
        float4 w = *reinterpret_cast<const float4*>(cw + (size_t)(h + 3) * 4);
        o.w = siluf(fmaf(w.w, c0.w, fmaf(w.z, c1.w, fmaf(w.y, c2.w, fmaf(w.x, c3.w, bb.w)))));
    }
    *reinterpret_cast<float4*>(xc + (size_t)tok * HIDDEN + h) = o;
    __half2 lo = __floats2half2_rn(o.x, o.y);
    __half2 hi = __floats2half2_rn(o.z, o.w);
    *reinterpret_cast<uint2*>(xc16 + (size_t)tok * HIDDEN + h) =
        make_uint2(*reinterpret_cast<uint32_t*>(&lo), *reinterpret_cast<uint32_t*>(&hi));
}

// ---------------------------------------------------------------------------
// Chunked scan (gate nonlinearity fused); gates in fp16
// ---------------------------------------------------------------------------
__device__ __forceinline__ void gate_ab(float rec, float inp, float sp, float xcv,
                                        float& a, float& bp)
{
    a = __expf(-sp * sigmoidf_(rec));
    float beta = sqrtf(1.0f - a * a + 1e-8f) * sigmoidf_(inp);
    bp = beta * xcv;
}

__global__ void scanA_k(const __half* __restrict__ gates,
                        const float* __restrict__ xc,
                        const float* __restrict__ Lambda,
                        float* __restrict__ chA, float* __restrict__ chB)
{
    int id = blockIdx.x * blockDim.x + threadIdx.x;
    if (id >= NCH * NCHUNK) return;
    int c     = id & (NCH - 1);
    int chunk = id >> 14;
    int b = c >> 9;
    int h = c & (HIDDEN - 1);
    float sp = log1pf(__expf(Lambda[h]));

    size_t tok0 = (size_t)b * SEQ + chunk * TCHUNK;
    float A = 1.0f, Bv = 0.0f;
    #pragma unroll 4
    for (int tt = 0; tt < TCHUNK; tt++) {
        size_t tok = tok0 + tt;
        float rec = __half2float(gates[tok * 1024 + h]);
        float inp = __half2float(gates[tok * 1024 + 512 + h]);
        float a, bp;
        gate_ab(rec, inp, sp, xc[tok * HIDDEN + h], a, bp);
        A *= a;
        Bv = fmaf(a, Bv, bp);
    }
    chA[id] = A;
    chB[id] = Bv;
}

__global__ void scanB_k(const float* __restrict__ chA, const float* __restrict__ chB,
                        float* __restrict__ pref)
{
    int c = blockIdx.x * blockDim.x + threadIdx.x;
    if (c >= NCH) return;
    float s = 0.0f;
    #pragma unroll
    for (int chunk = 0; chunk < NCHUNK; chunk++) {
        pref[chunk * NCH + c] = s;
        s = fmaf(chA[chunk * NCH + c], s, chB[chunk * NCH + c]);
    }
}

__global__ void scanC_k(const __half* __restrict__ gates,
                        const float* __restrict__ xc,
                        const float* __restrict__ xz,
                        const float* __restrict__ Lambda,
                        const float* __restrict__ pref,
                        __half* __restrict__ gh16)
{
    int id = blockIdx.x * blockDim.x + threadIdx.x;
    if (id >= NCH * NCHUNK) return;
    int c     = id & (NCH - 1);
    int chunk = id >> 14;
    int b = c >> 9;
    int h = c & (HIDDEN - 1);
    float sp = log1pf(__expf(Lambda[h]));

    size_t tok0 = (size_t)b * SEQ + chunk * TCHUNK;
    float state = pref[id];
    #pragma unroll 4
    for (int tt = 0; tt < TCHUNK; tt++) {
        size_t tok = tok0 + tt;
        float rec = __half2float(gates[tok * 1024 + h]);
        float inp = __half2float(gates[tok * 1024 + 512 + h]);
        float a, bp;
        gate_ab(rec, inp, sp, xc[tok * HIDDEN + h], a, bp);
        state = fmaf(a, state, bp);
        float z = xz[tok * 1024 + 512 + h];
        gh16[tok * HIDDEN + h] = __float2half(state * siluf(z));
    }
}

// ---------------------------------------------------------------------------
// LayerNorm over D=256: out = LN(a + res) * gamma + beta (+ optional fp16 copy)
// ---------------------------------------------------------------------------
template<bool H16>
__global__ void ln_k(const float* __restrict__ a,
                     const float* __restrict__ res,
                     const float* __restrict__ gamma,
                     const float* __restrict__ beta,
                     float* __restrict__ out,
                     __half* __restrict__ out16)
{
    int tok = blockIdx.x;
    int i = threadIdx.x;
    size_t off = (size_t)tok * DMODEL + i;
    float v = a[off] + res[off];

    float s = v, s2 = v * v;
    #pragma unroll
    for (int o = 16; o > 0; o >>= 1) {
        s  += __shfl_xor_sync(0xffffffffu, s,  o);
        s2 += __shfl_xor_sync(0xffffffffu, s2, o);
    }
    __shared__ float sh[2][8];
    int w = i >> 5, l = i & 31;
    if (l == 0) { sh[0][w] = s; sh[1][w] = s2; }
    __syncthreads();
    if (w == 0) {
        float ts  = (l < 8) ? sh[0][l] : 0.0f;
        float ts2 = (l < 8) ? sh[1][l] : 0.0f;
        #pragma unroll
        for (int o = 4; o > 0; o >>= 1) {
            ts  += __shfl_xor_sync(0xffffffffu, ts,  o);
            ts2 += __shfl_xor_sync(0xffffffffu, ts2, o);
        }
        if (l == 0) { sh[0][0] = ts; sh[1][0] = ts2; }
    }
    __syncthreads();
    float mean = sh[0][0] * (1.0f / DMODEL);
    float var  = sh[1][0] * (1.0f / DMODEL) - mean * mean;
    float inv  = rsqrtf(var + 1e-12f);
    float o = (v - mean) * inv * gamma[i] + beta[i];
    out[off] = o;
    if (H16) out16[off] = __float2half(o);
}

// ---------------------------------------------------------------------------
// Host launcher
// ---------------------------------------------------------------------------
extern "C" void kernel_launch(void* const* d_in, const int* in_sizes, int n_in,
                              void* d_out, int out_size)
{
    const float* x      = (const float*)d_in[0];
    const float* w_in   = (const float*)d_in[1];
    const float* conv_w = (const float*)d_in[2];
    const float* conv_b = (const float*)d_in[3];
    const float* w_gate = (const float*)d_in[4];
    const float* b_gate = (const float*)d_in[5];
    const float* Lambda = (const float*)d_in[6];
    const float* w_out  = (const float*)d_in[7];
    const float* ln1_g  = (const float*)d_in[8];
    const float* ln1_b  = (const float*)d_in[9];
    const float* ffn_w1 = (const float*)d_in[10];
    const float* ffn_b1 = (const float*)d_in[11];
    const float* ffn_w2 = (const float*)d_in[12];
    const float* ffn_b2 = (const float*)d_in[13];
    const float* ln2_g  = (const float*)d_in[14];
    const float* ln2_b  = (const float*)d_in[15];
    float* out = (float*)d_out;

    float  *xz, *xc, *y, *hs, *ff, *chA, *chB, *pref;
    __half *x16, *xc16, *gates16, *gh16, *hs16, *u16;
    __half *wt_in, *wt_gates, *wt_out, *wt_f1, *wt_f2;
    cudaGetSymbolAddress((void**)&xz,      g_xz);
    cudaGetSymbolAddress((void**)&xc,      g_xc);
    cudaGetSymbolAddress((void**)&xc16,    g_xc16);
    cudaGetSymbolAddress((void**)&x16,     g_x16);
    cudaGetSymbolAddress((void**)&gates16, g_gates16);
    cudaGetSymbolAddress((void**)&gh16,    g_gh16);
    cudaGetSymbolAddress((void**)&y,       g_y);
    cudaGetSymbolAddress((void**)&hs,      g_hs);
    cudaGetSymbolAddress((void**)&hs16,    g_hs16);
    cudaGetSymbolAddress((void**)&u16,     g_u16);
    cudaGetSymbolAddress((void**)&ff,      g_ff);
    cudaGetSymbolAddress((void**)&chA,     g_chA);
    cudaGetSymbolAddress((void**)&chB,     g_chB);
    cudaGetSymbolAddress((void**)&pref,    g_pref);
    cudaGetSymbolAddress((void**)&wt_in,    g_wt_in);
    cudaGetSymbolAddress((void**)&wt_gates, g_wt_gates);
    cudaGetSymbolAddress((void**)&wt_out,   g_wt_out);
    cudaGetSymbolAddress((void**)&wt_f1,    g_wt_f1);
    cudaGetSymbolAddress((void**)&wt_f2,    g_wt_f2);

    const int M = TOKENS;
    dim3 tb(32, 8);

    // 0) weight transpose+convert, x convert
    transpose_cvt_k<<<dim3(1024/32, 256/32),  tb>>>(w_in,   wt_in,    256, 1024);
    transpose_cvt_k<<<dim3(1024/32, 512/32),  tb>>>(w_gate, wt_gates, 512, 1024);
    transpose_cvt_k<<<dim3(256/32,  512/32),  tb>>>(w_out,  wt_out,   512, 256);
    transpose_cvt_k<<<dim3(1024/32, 256/32),  tb>>>(ffn_w1, wt_f1,    256, 1024);
    transpose_cvt_k<<<dim3(256/32, 1024/32),  tb>>>(ffn_w2, wt_f2,   1024, 256);
    cvt_x_k<<<(TOKENS * DMODEL / 4 + 255) / 256, 256>>>(x, x16, TOKENS * DMODEL / 4);

    // 1) xz = x @ w_in            (fp32 out)
    hgemm<0><<<dim3(1024/128, M/128), 256>>>(x16, wt_in, nullptr, xz, nullptr, M, 1024, 256);

    // 2) conv + silu -> xc, xc16
    conv_silu_k<<<(TOKENS * (HIDDEN/4)) / 256, 256>>>(xz, conv_w, conv_b, xc, xc16);

    // 3) gates16 = xc @ w_gates + b_gates   (fp16 out)
    hgemm<3><<<dim3(1024/128, M/128), 256>>>(xc16, wt_gates, b_gate, nullptr, gates16, M, 1024, 512);

    // 4-6) chunked scan -> gh16
    scanA_k<<<(NCH * NCHUNK) / 256, 256>>>(gates16, xc, Lambda, chA, chB);
    scanB_k<<<NCH / 256, 256>>>(chA, chB, pref);
    scanC_k<<<(NCH * NCHUNK) / 256, 256>>>(gates16, xc, xz, Lambda, pref, gh16);

    // 7) y = gh @ w_out           (fp32 out)
    hgemm<0><<<dim3(256/128, M/128), 256>>>(gh16, wt_out, nullptr, y, nullptr, M, 256, 512);

    // 8) hs = LN1(y + x), + fp16 copy
    ln_k<true><<<TOKENS, DMODEL>>>(y, x, ln1_g, ln1_b, hs, hs16);

    // 9) u16 = silu(hs @ ffn_w1 + b1)   (fp16 out)
    hgemm<2><<<dim3(1024/128, M/128), 256>>>(hs16, wt_f1, ffn_b1, nullptr, u16, M, 1024, 256);

    // 10) ff = u @ ffn_w2 + b2    (fp32 out)
    hgemm<1><<<dim3(256/128, M/128), 256>>>(u16, wt_f2, ffn_b2, ff, nullptr, M, 256, 1024);

    // 11) out = LN2(ff + hs)
    ln_k<false><<<TOKENS, DMODEL>>>(ff, hs, ln2_g, ln2_b, out, nullptr);
}